// round 13
// baseline (speedup 1.0000x reference)
#include <cuda_runtime.h>

#define KS   13
#define RAD  6
#define TW   16
#define TH   8            // 16x8 outputs per block; 64 threads, 2 vertical outputs each
#define PW   (TW + 2*RAD) // 28
#define PH   (TH + 2*RAD) // 20
#define IMH  256
#define IMW  256
#define NC   4
#define NB   2
#define NT   64

__device__ __forceinline__ float fast_ex2(float x) {
    float r; asm("ex2.approx.ftz.f32 %0, %1;" : "=f"(r) : "f"(x)); return r;
}

// 13 taps of one row for one center: accumulate row partials (no spatial row term)
#define ROW13(RP, NCX, NCY, NCZ, NCW, PW_, PU_, PV_, PX_, PY_)                 \
    _Pragma("unroll")                                                          \
    for (int ix = 0; ix < KS; ix++) {                                          \
        float4 p = (RP)[ix];                                                   \
        float d0 = __fmaf_rn(p.x, SC, NCX);                                    \
        float d1 = __fmaf_rn(p.y, SC, NCY);                                    \
        float d2 = __fmaf_rn(p.z, SC, NCZ);                                    \
        float d3 = __fmaf_rn(p.w, SC, NCW);                                    \
        float m01 = fmaxf(fabsf(d0), fabsf(d1));                               \
        float m23 = fmaxf(fabsf(d2), fabsf(d3));                               \
        float dd  = m01 + m23;                                                 \
        float w   = fast_ex2(__fmaf_rn(dd, -dd, Tx[ix]));                      \
        PW_ += w;                                                              \
        PU_ = __fmaf_rn(w, p.x, PU_);                                          \
        PV_ = __fmaf_rn(w, p.y, PV_);                                          \
        PX_ = __fmaf_rn(w, p.z, PX_);                                          \
        PY_ = __fmaf_rn(w, p.w, PY_);                                          \
    }

__global__ __launch_bounds__(NT)
void bilateral13_v13(const float* __restrict__ x, float* __restrict__ out) {
    __shared__ float4 tile[PH][PW];   // (u01, v01, u23, v23) basis, ~9KB

    const int tid = threadIdx.x;      // 0..63
    const int b   = blockIdx.z;
    const int tx0 = blockIdx.x * TW;
    const int ty0 = blockIdx.y * TH;

    const float K2 = (-0.5f / 9.0f) * 1.4426950408889634f;  // log2 domain
    const float SC = 0.28311592f;                           // sqrt(-K2)

    // ---- cooperative load: reflect pad + (u,v) basis change ----------------
    const float* xb = x + (size_t)b * NC * IMH * IMW;
    #pragma unroll
    for (int it = 0; it < (PH * PW + NT - 1) / NT; it++) {
        int i = tid + it * NT;
        if (i < PH * PW) {
            int py = i / PW, px = i % PW;
            int gy = ty0 + py - RAD;
            int gx = tx0 + px - RAD;
            gy = (gy < 0) ? -gy : ((gy >= IMH) ? (2 * IMH - 2 - gy) : gy);
            gx = (gx < 0) ? -gx : ((gx >= IMW) ? (2 * IMW - 2 - gx) : gx);
            int g = gy * IMW + gx;
            float p0 = xb[0 * IMH * IMW + g];
            float p1 = xb[1 * IMH * IMW + g];
            float p2 = xb[2 * IMH * IMW + g];
            float p3 = xb[3 * IMH * IMW + g];
            float4 v;
            v.x = p0 + p1;
            v.y = p0 - p1;
            v.z = p2 + p3;
            v.w = p2 - p3;
            tile[py][px] = v;
        }
    }
    __syncthreads();

    // ---- per-thread: two vertically adjacent outputs -----------------------
    const int lx  = tid & (TW - 1);   // 0..15
    const int lyP = tid >> 4;         // 0..3 -> output rows 2lyP, 2lyP+1
    const int b0  = 2 * lyP;          // first window row (tile coords)

    const float4 c1 = tile[b0 + RAD][lx + RAD];
    const float4 c2 = tile[b0 + RAD + 1][lx + RAD];
    const float nc1x = -SC * c1.x, nc1y = -SC * c1.y, nc1z = -SC * c1.z, nc1w = -SC * c1.w;
    const float nc2x = -SC * c2.x, nc2y = -SC * c2.y, nc2z = -SC * c2.z, nc2w = -SC * c2.w;

    // column spatial term, register-resident (constant indexing only)
    float Tx[KS];
    #pragma unroll
    for (int i = 0; i < KS; i++) {
        float fi = (float)(i - RAD);
        Tx[i] = K2 * fi * fi;
    }

    // totals
    float s1 = 0.f, U1 = 0.f, V1 = 0.f, X1 = 0.f, Y1 = 0.f;
    float s2 = 0.f, U2 = 0.f, V2 = 0.f, X2 = 0.f, Y2 = 0.f;

    const float gEdge = fast_ex2(K2 * 36.0f);   // ex2(Ty) at |iy-6| = 6

    // ---- j = 0: center1 only (its spatial row 0) ---------------------------
    {
        const float4* rp = &tile[b0][lx];
        float Pw = 0.f, PU = 0.f, PV = 0.f, PX = 0.f, PY = 0.f;
        ROW13(rp, nc1x, nc1y, nc1z, nc1w, Pw, PU, PV, PX, PY)
        s1 = __fmaf_rn(gEdge, Pw, s1);
        U1 = __fmaf_rn(gEdge, PU, U1);
        V1 = __fmaf_rn(gEdge, PV, V1);
        X1 = __fmaf_rn(gEdge, PX, X1);
        Y1 = __fmaf_rn(gEdge, PY, Y1);
    }

    // ---- j = 1..12: both centers share the row load; 2 rows in flight ------
    #pragma unroll 2
    for (int j = 1; j <= 12; j++) {
        const float4* rp = &tile[b0 + j][lx];
        float P1w = 0.f, P1U = 0.f, P1V = 0.f, P1X = 0.f, P1Y = 0.f;
        float P2w = 0.f, P2U = 0.f, P2V = 0.f, P2X = 0.f, P2Y = 0.f;
        #pragma unroll
        for (int ix = 0; ix < KS; ix++) {
            float4 p = rp[ix];
            // center 1
            {
                float d0 = __fmaf_rn(p.x, SC, nc1x);
                float d1 = __fmaf_rn(p.y, SC, nc1y);
                float d2 = __fmaf_rn(p.z, SC, nc1z);
                float d3 = __fmaf_rn(p.w, SC, nc1w);
                float m01 = fmaxf(fabsf(d0), fabsf(d1));
                float m23 = fmaxf(fabsf(d2), fabsf(d3));
                float dd  = m01 + m23;
                float w   = fast_ex2(__fmaf_rn(dd, -dd, Tx[ix]));
                P1w += w;
                P1U = __fmaf_rn(w, p.x, P1U);
                P1V = __fmaf_rn(w, p.y, P1V);
                P1X = __fmaf_rn(w, p.z, P1X);
                P1Y = __fmaf_rn(w, p.w, P1Y);
            }
            // center 2
            {
                float d0 = __fmaf_rn(p.x, SC, nc2x);
                float d1 = __fmaf_rn(p.y, SC, nc2y);
                float d2 = __fmaf_rn(p.z, SC, nc2z);
                float d3 = __fmaf_rn(p.w, SC, nc2w);
                float m01 = fmaxf(fabsf(d0), fabsf(d1));
                float m23 = fmaxf(fabsf(d2), fabsf(d3));
                float dd  = m01 + m23;
                float w   = fast_ex2(__fmaf_rn(dd, -dd, Tx[ix]));
                P2w += w;
                P2U = __fmaf_rn(w, p.x, P2U);
                P2V = __fmaf_rn(w, p.y, P2V);
                P2X = __fmaf_rn(w, p.z, P2X);
                P2Y = __fmaf_rn(w, p.w, P2Y);
            }
        }
        float a1 = (float)(j - 6);        // center1 spatial row offset
        float a2 = (float)(j - 7);        // center2 spatial row offset
        float g1 = fast_ex2(K2 * a1 * a1);
        float g2 = fast_ex2(K2 * a2 * a2);
        s1 = __fmaf_rn(g1, P1w, s1);
        U1 = __fmaf_rn(g1, P1U, U1);
        V1 = __fmaf_rn(g1, P1V, V1);
        X1 = __fmaf_rn(g1, P1X, X1);
        Y1 = __fmaf_rn(g1, P1Y, Y1);
        s2 = __fmaf_rn(g2, P2w, s2);
        U2 = __fmaf_rn(g2, P2U, U2);
        V2 = __fmaf_rn(g2, P2V, V2);
        X2 = __fmaf_rn(g2, P2X, X2);
        Y2 = __fmaf_rn(g2, P2Y, Y2);
    }

    // ---- j = 13: center2 only (its spatial row 12) -------------------------
    {
        const float4* rp = &tile[b0 + 13][lx];
        float Pw = 0.f, PU = 0.f, PV = 0.f, PX = 0.f, PY = 0.f;
        ROW13(rp, nc2x, nc2y, nc2z, nc2w, Pw, PU, PV, PX, PY)
        s2 = __fmaf_rn(gEdge, Pw, s2);
        U2 = __fmaf_rn(gEdge, PU, U2);
        V2 = __fmaf_rn(gEdge, PV, V2);
        X2 = __fmaf_rn(gEdge, PX, X2);
        Y2 = __fmaf_rn(gEdge, PY, Y2);
    }

    // ---- epilogue: undo basis change, normalize ----------------------------
    float* ob = out + (size_t)b * NC * IMH * IMW;
    const int y1 = ty0 + 2 * lyP;
    const int o1 = y1 * IMW + tx0 + lx;
    const int o2 = o1 + IMW;

    const float h1 = __fdividef(0.5f, s1);
    ob[0 * IMH * IMW + o1] = (U1 + V1) * h1;
    ob[1 * IMH * IMW + o1] = (U1 - V1) * h1;
    ob[2 * IMH * IMW + o1] = (X1 + Y1) * h1;
    ob[3 * IMH * IMW + o1] = (X1 - Y1) * h1;

    const float h2 = __fdividef(0.5f, s2);
    ob[0 * IMH * IMW + o2] = (U2 + V2) * h2;
    ob[1 * IMH * IMW + o2] = (U2 - V2) * h2;
    ob[2 * IMH * IMW + o2] = (X2 + Y2) * h2;
    ob[3 * IMH * IMW + o2] = (X2 - Y2) * h2;
}

extern "C" void kernel_launch(void* const* d_in, const int* in_sizes, int n_in,
                              void* d_out, int out_size) {
    const float* x = (const float*)d_in[0];
    float* out = (float*)d_out;
    dim3 grid(IMW / TW, IMH / TH, NB);   // 16 x 32 x 2 = 1024 blocks
    bilateral13_v13<<<grid, NT>>>(x, out);
}

// round 14
// speedup vs baseline: 1.0274x; 1.0274x over previous
#include <cuda_runtime.h>

#define KS   13
#define RAD  6
#define TW   16
#define TH   8            // 16x8 outputs per block; 64 threads, 2 vertical outputs each
#define PW   (TW + 2*RAD) // 28
#define PH   (TH + 2*RAD) // 20
#define IMH  256
#define IMW  256
#define NC   4
#define NB   2
#define NT   64

__device__ __forceinline__ float fast_ex2(float x) {
    float r; asm("ex2.approx.ftz.f32 %0, %1;" : "=f"(r) : "f"(x)); return r;
}

__global__ __launch_bounds__(NT, 2)   // reg cap -> 255: regs are free (grid/smem-limited occ)
void bilateral13_v14(const float* __restrict__ x, float* __restrict__ out) {
    __shared__ float4 tile[PH][PW];   // (u01, v01, u23, v23) basis, ~9KB

    const int tid = threadIdx.x;      // 0..63
    const int b   = blockIdx.z;
    const int tx0 = blockIdx.x * TW;
    const int ty0 = blockIdx.y * TH;

    const float K2 = (-0.5f / 9.0f) * 1.4426950408889634f;  // log2 domain
    const float SC = 0.28311592f;                           // sqrt(-K2)

    // ---- cooperative load: reflect pad + (u,v) basis change ----------------
    const float* xb = x + (size_t)b * NC * IMH * IMW;
    #pragma unroll
    for (int it = 0; it < (PH * PW + NT - 1) / NT; it++) {
        int i = tid + it * NT;
        if (i < PH * PW) {
            int py = i / PW, px = i % PW;
            int gy = ty0 + py - RAD;
            int gx = tx0 + px - RAD;
            gy = (gy < 0) ? -gy : ((gy >= IMH) ? (2 * IMH - 2 - gy) : gy);
            gx = (gx < 0) ? -gx : ((gx >= IMW) ? (2 * IMW - 2 - gx) : gx);
            int g = gy * IMW + gx;
            float p0 = xb[0 * IMH * IMW + g];
            float p1 = xb[1 * IMH * IMW + g];
            float p2 = xb[2 * IMH * IMW + g];
            float p3 = xb[3 * IMH * IMW + g];
            float4 v;
            v.x = p0 + p1;
            v.y = p0 - p1;
            v.z = p2 + p3;
            v.w = p2 - p3;
            tile[py][px] = v;
        }
    }
    __syncthreads();

    // ---- per-thread: two vertically adjacent outputs -----------------------
    const int lx  = tid & (TW - 1);   // 0..15
    const int lyP = tid >> 4;         // 0..3 -> output rows 2lyP, 2lyP+1
    const int b0  = 2 * lyP;          // first window row (tile coords)

    const float4 c1 = tile[b0 + RAD][lx + RAD];
    const float4 c2 = tile[b0 + RAD + 1][lx + RAD];
    const float nc1x = -SC * c1.x, nc1y = -SC * c1.y, nc1z = -SC * c1.z, nc1w = -SC * c1.w;
    const float nc2x = -SC * c2.x, nc2y = -SC * c2.y, nc2z = -SC * c2.z, nc2w = -SC * c2.w;

    // column spatial term, register-resident (constant indexing only)
    float Tx[KS];
    #pragma unroll
    for (int i = 0; i < KS; i++) {
        float fi = (float)(i - RAD);
        Tx[i] = K2 * fi * fi;
    }

    // totals
    float s1 = 0.f, U1 = 0.f, V1 = 0.f, X1 = 0.f, Y1 = 0.f;
    float s2 = 0.f, U2 = 0.f, V2 = 0.f, X2 = 0.f, Y2 = 0.f;

    const float gEdge = fast_ex2(K2 * 36.0f);   // ex2(Ty) at |iy-6| = 6

    // ---- j = 0: center1 only (its spatial row 0) ---------------------------
    {
        const float4* rp = &tile[b0][lx];
        float4 q[KS];
        #pragma unroll
        for (int ix = 0; ix < KS; ix++) q[ix] = rp[ix];   // batched LDS: MLP=13
        float Pw = 0.f, PU = 0.f, PV = 0.f, PX = 0.f, PY = 0.f;
        #pragma unroll
        for (int ix = 0; ix < KS; ix++) {
            float4 p = q[ix];
            float d0 = __fmaf_rn(p.x, SC, nc1x);
            float d1 = __fmaf_rn(p.y, SC, nc1y);
            float d2 = __fmaf_rn(p.z, SC, nc1z);
            float d3 = __fmaf_rn(p.w, SC, nc1w);
            float m01 = fmaxf(fabsf(d0), fabsf(d1));
            float m23 = fmaxf(fabsf(d2), fabsf(d3));
            float dd  = m01 + m23;
            float w   = fast_ex2(__fmaf_rn(dd, -dd, Tx[ix]));
            Pw += w;
            PU = __fmaf_rn(w, p.x, PU);
            PV = __fmaf_rn(w, p.y, PV);
            PX = __fmaf_rn(w, p.z, PX);
            PY = __fmaf_rn(w, p.w, PY);
        }
        s1 = __fmaf_rn(gEdge, Pw, s1);
        U1 = __fmaf_rn(gEdge, PU, U1);
        V1 = __fmaf_rn(gEdge, PV, V1);
        X1 = __fmaf_rn(gEdge, PX, X1);
        Y1 = __fmaf_rn(gEdge, PY, Y1);
    }

    // ---- j = 1..12: both centers share the batched row load ----------------
    #pragma unroll 2
    for (int j = 1; j <= 12; j++) {
        const float4* rp = &tile[b0 + j][lx];
        float4 q[KS];
        #pragma unroll
        for (int ix = 0; ix < KS; ix++) q[ix] = rp[ix];   // batched LDS: MLP=13
        float P1w = 0.f, P1U = 0.f, P1V = 0.f, P1X = 0.f, P1Y = 0.f;
        float P2w = 0.f, P2U = 0.f, P2V = 0.f, P2X = 0.f, P2Y = 0.f;
        #pragma unroll
        for (int ix = 0; ix < KS; ix++) {
            float4 p = q[ix];
            // center 1
            {
                float d0 = __fmaf_rn(p.x, SC, nc1x);
                float d1 = __fmaf_rn(p.y, SC, nc1y);
                float d2 = __fmaf_rn(p.z, SC, nc1z);
                float d3 = __fmaf_rn(p.w, SC, nc1w);
                float m01 = fmaxf(fabsf(d0), fabsf(d1));
                float m23 = fmaxf(fabsf(d2), fabsf(d3));
                float dd  = m01 + m23;
                float w   = fast_ex2(__fmaf_rn(dd, -dd, Tx[ix]));
                P1w += w;
                P1U = __fmaf_rn(w, p.x, P1U);
                P1V = __fmaf_rn(w, p.y, P1V);
                P1X = __fmaf_rn(w, p.z, P1X);
                P1Y = __fmaf_rn(w, p.w, P1Y);
            }
            // center 2
            {
                float d0 = __fmaf_rn(p.x, SC, nc2x);
                float d1 = __fmaf_rn(p.y, SC, nc2y);
                float d2 = __fmaf_rn(p.z, SC, nc2z);
                float d3 = __fmaf_rn(p.w, SC, nc2w);
                float m01 = fmaxf(fabsf(d0), fabsf(d1));
                float m23 = fmaxf(fabsf(d2), fabsf(d3));
                float dd  = m01 + m23;
                float w   = fast_ex2(__fmaf_rn(dd, -dd, Tx[ix]));
                P2w += w;
                P2U = __fmaf_rn(w, p.x, P2U);
                P2V = __fmaf_rn(w, p.y, P2V);
                P2X = __fmaf_rn(w, p.z, P2X);
                P2Y = __fmaf_rn(w, p.w, P2Y);
            }
        }
        float a1 = (float)(j - 6);        // center1 spatial row offset
        float a2 = (float)(j - 7);        // center2 spatial row offset
        float g1 = fast_ex2(K2 * a1 * a1);
        float g2 = fast_ex2(K2 * a2 * a2);
        s1 = __fmaf_rn(g1, P1w, s1);
        U1 = __fmaf_rn(g1, P1U, U1);
        V1 = __fmaf_rn(g1, P1V, V1);
        X1 = __fmaf_rn(g1, P1X, X1);
        Y1 = __fmaf_rn(g1, P1Y, Y1);
        s2 = __fmaf_rn(g2, P2w, s2);
        U2 = __fmaf_rn(g2, P2U, U2);
        V2 = __fmaf_rn(g2, P2V, V2);
        X2 = __fmaf_rn(g2, P2X, X2);
        Y2 = __fmaf_rn(g2, P2Y, Y2);
    }

    // ---- j = 13: center2 only (its spatial row 12) -------------------------
    {
        const float4* rp = &tile[b0 + 13][lx];
        float4 q[KS];
        #pragma unroll
        for (int ix = 0; ix < KS; ix++) q[ix] = rp[ix];
        float Pw = 0.f, PU = 0.f, PV = 0.f, PX = 0.f, PY = 0.f;
        #pragma unroll
        for (int ix = 0; ix < KS; ix++) {
            float4 p = q[ix];
            float d0 = __fmaf_rn(p.x, SC, nc2x);
            float d1 = __fmaf_rn(p.y, SC, nc2y);
            float d2 = __fmaf_rn(p.z, SC, nc2z);
            float d3 = __fmaf_rn(p.w, SC, nc2w);
            float m01 = fmaxf(fabsf(d0), fabsf(d1));
            float m23 = fmaxf(fabsf(d2), fabsf(d3));
            float dd  = m01 + m23;
            float w   = fast_ex2(__fmaf_rn(dd, -dd, Tx[ix]));
            Pw += w;
            PU = __fmaf_rn(w, p.x, PU);
            PV = __fmaf_rn(w, p.y, PV);
            PX = __fmaf_rn(w, p.z, PX);
            PY = __fmaf_rn(w, p.w, PY);
        }
        s2 = __fmaf_rn(gEdge, Pw, s2);
        U2 = __fmaf_rn(gEdge, PU, U2);
        V2 = __fmaf_rn(gEdge, PV, V2);
        X2 = __fmaf_rn(gEdge, PX, X2);
        Y2 = __fmaf_rn(gEdge, PY, Y2);
    }

    // ---- epilogue: undo basis change, normalize ----------------------------
    float* ob = out + (size_t)b * NC * IMH * IMW;
    const int y1 = ty0 + 2 * lyP;
    const int o1 = y1 * IMW + tx0 + lx;
    const int o2 = o1 + IMW;

    const float h1 = __fdividef(0.5f, s1);
    ob[0 * IMH * IMW + o1] = (U1 + V1) * h1;
    ob[1 * IMH * IMW + o1] = (U1 - V1) * h1;
    ob[2 * IMH * IMW + o1] = (X1 + Y1) * h1;
    ob[3 * IMH * IMW + o1] = (X1 - Y1) * h1;

    const float h2 = __fdividef(0.5f, s2);
    ob[0 * IMH * IMW + o2] = (U2 + V2) * h2;
    ob[1 * IMH * IMW + o2] = (U2 - V2) * h2;
    ob[2 * IMH * IMW + o2] = (X2 + Y2) * h2;
    ob[3 * IMH * IMW + o2] = (X2 - Y2) * h2;
}

extern "C" void kernel_launch(void* const* d_in, const int* in_sizes, int n_in,
                              void* d_out, int out_size) {
    const float* x = (const float*)d_in[0];
    float* out = (float*)d_out;
    dim3 grid(IMW / TW, IMH / TH, NB);   // 16 x 32 x 2 = 1024 blocks
    bilateral13_v14<<<grid, NT>>>(x, out);
}